// round 10
// baseline (speedup 1.0000x reference)
#include <cuda_runtime.h>
#include <math.h>

// Problem constants
#define NN   16384
#define HID  128
#define PROP 64
#define SPACE 4
#define KNB  40
#define NLAYERS 4
#define FULLMASK 0xFFFFFFFFu

// Scratch (static device allocations; no cudaMalloc allowed)
__device__ float g_x[NN * HID];
__device__ float g_y[NN * HID];
__device__ float g_s[NN * SPACE];
__device__ float g_h[NN * PROP];
__device__ float g_agg[NN * HID];
__device__ float g_w[NN * KNB];
__device__ int   g_idx[NN * KNB];

// Device-side buffer resolution: keeps kernel_launch free of any host API
// besides kernel launches. ids: 0=g_x, 1=g_y, 2=g_agg, 3=g_h, 4=g_s, -1=arg.
__device__ __forceinline__ const float* resolve_c(const float* p, int id) {
    switch (id) {
        case 0: return g_x;
        case 1: return g_y;
        case 2: return g_agg;
        case 3: return g_h;
        case 4: return g_s;
        default: return p;
    }
}
__device__ __forceinline__ float* resolve_w(float* p, int id) {
    switch (id) {
        case 0: return g_x;
        case 1: return g_y;
        case 2: return g_agg;
        case 3: return g_h;
        case 4: return g_s;
        default: return p;
    }
}

// Monotone float <-> uint key maps (for redux.max over distances).
__device__ __forceinline__ unsigned fkey(float f) {
    unsigned u = __float_as_uint(f);
    return u ^ ((unsigned)((int)u >> 31) | 0x80000000u);
}
__device__ __forceinline__ float unfkey(unsigned k) {
    unsigned m = (k & 0x80000000u) ? 0x80000000u : 0xFFFFFFFFu;
    return __uint_as_float(k ^ m);
}

// ---------------------------------------------------------------------------
// Tiled SGEMM: C[N x MD] = act(A[N x KD] @ W[KD x MD] + b)
// 256 threads: thread (c = t%MD, h = t/MD) owns column c for RPT=MD/8 rows.
// k-step 8 with depth-2 W prefetch (issue k+16 loads while computing k).
// ---------------------------------------------------------------------------
template <int KD, int MD, bool RELU>
__global__ void __launch_bounds__(256) gemm_k(const float* __restrict__ Ap, int aid,
                                              const float* __restrict__ W,
                                              const float* __restrict__ B,
                                              float* __restrict__ Cp, int cid) {
    constexpr int RPT = MD / 8;  // rows per thread (MD=128 -> 16, MD=64 -> 8)
    const float* __restrict__ A = resolve_c(Ap, aid);
    float* __restrict__ C = resolve_w(Cp, cid);

    __shared__ float As[32 * KD];
    const int t = threadIdx.x;
    const int c = t % MD;
    const int h = t / MD;
    const int row0 = blockIdx.x * 32;

    {
        const float4* src = reinterpret_cast<const float4*>(A + row0 * KD);
        float4* dst = reinterpret_cast<float4*>(As);
        for (int i = t; i < 8 * KD; i += 256) dst[i] = src[i];
    }
    __syncthreads();

    float acc[RPT];
#pragma unroll
    for (int r = 0; r < RPT; ++r) acc[r] = 0.f;

    const float* Asb = As + (h * RPT) * KD;

    if constexpr (KD % 16 == 0) {
        float w[8], p[8];
#pragma unroll
        for (int q = 0; q < 8; ++q) w[q] = W[q * MD + c];
#pragma unroll
        for (int q = 0; q < 8; ++q) p[q] = W[(8 + q) * MD + c];

        for (int k = 0; k < KD; k += 8) {
            float n[8];
#pragma unroll
            for (int q = 0; q < 8; ++q) n[q] = 0.f;
            if (k + 16 < KD) {
#pragma unroll
                for (int q = 0; q < 8; ++q) n[q] = W[(k + 16 + q) * MD + c];
            }
#pragma unroll
            for (int r = 0; r < RPT; ++r) {
                float4 a0 = *reinterpret_cast<const float4*>(&Asb[r * KD + k]);
                float4 a1 = *reinterpret_cast<const float4*>(&Asb[r * KD + k + 4]);
                float v = acc[r];
                v = fmaf(a0.x, w[0], v);
                v = fmaf(a0.y, w[1], v);
                v = fmaf(a0.z, w[2], v);
                v = fmaf(a0.w, w[3], v);
                v = fmaf(a1.x, w[4], v);
                v = fmaf(a1.y, w[5], v);
                v = fmaf(a1.z, w[6], v);
                v = fmaf(a1.w, w[7], v);
                acc[r] = v;
            }
#pragma unroll
            for (int q = 0; q < 8; ++q) { w[q] = p[q]; p[q] = n[q]; }
        }
    } else {
        for (int k = 0; k < KD; ++k) {
            float wv = W[k * MD + c];
#pragma unroll
            for (int r = 0; r < RPT; ++r) acc[r] = fmaf(Asb[r * KD + k], wv, acc[r]);
        }
    }

    float bb = B[c];
#pragma unroll
    for (int r = 0; r < RPT; ++r) {
        float v = acc[r] + bb;
        if (RELU) v = fmaxf(v, 0.f);
        C[(row0 + h * RPT + r) * MD + c] = v;
    }
}

// ---------------------------------------------------------------------------
// Two-source SGEMM for lin_out: g_x = [g_y | g_agg] @ W + b, KD=256, MD=128.
// ---------------------------------------------------------------------------
__global__ void __launch_bounds__(256) gemm2_k(const float* __restrict__ W,
                                               const float* __restrict__ B) {
    const float* __restrict__ A1 = g_y;
    const float* __restrict__ A2 = g_agg;
    float* __restrict__ C = g_x;

    __shared__ float As[32 * 256];
    const int t = threadIdx.x;
    const int c = t % 128;
    const int h = t / 128;
    const int row0 = blockIdx.x * 32;

    {
        const float4* s1 = reinterpret_cast<const float4*>(A1 + row0 * 128);
        const float4* s2 = reinterpret_cast<const float4*>(A2 + row0 * 128);
        float4* dst = reinterpret_cast<float4*>(As);
        for (int i = t; i < 32 * 32; i += 256) {
            int r = i >> 5, kq = i & 31;
            dst[r * 64 + kq]      = s1[r * 32 + kq];
            dst[r * 64 + 32 + kq] = s2[r * 32 + kq];
        }
    }
    __syncthreads();

    float acc[16];
#pragma unroll
    for (int r = 0; r < 16; ++r) acc[r] = 0.f;

    const float* Asb = As + (h * 16) * 256;

    float w[8], p[8];
#pragma unroll
    for (int q = 0; q < 8; ++q) w[q] = W[q * 128 + c];
#pragma unroll
    for (int q = 0; q < 8; ++q) p[q] = W[(8 + q) * 128 + c];

    for (int k = 0; k < 256; k += 8) {
        float n[8];
#pragma unroll
        for (int q = 0; q < 8; ++q) n[q] = 0.f;
        if (k + 16 < 256) {
#pragma unroll
            for (int q = 0; q < 8; ++q) n[q] = W[(k + 16 + q) * 128 + c];
        }
#pragma unroll
        for (int r = 0; r < 16; ++r) {
            float4 a0 = *reinterpret_cast<const float4*>(&Asb[r * 256 + k]);
            float4 a1 = *reinterpret_cast<const float4*>(&Asb[r * 256 + k + 4]);
            float v = acc[r];
            v = fmaf(a0.x, w[0], v);
            v = fmaf(a0.y, w[1], v);
            v = fmaf(a0.z, w[2], v);
            v = fmaf(a0.w, w[3], v);
            v = fmaf(a1.x, w[4], v);
            v = fmaf(a1.y, w[5], v);
            v = fmaf(a1.z, w[6], v);
            v = fmaf(a1.w, w[7], v);
            acc[r] = v;
        }
#pragma unroll
        for (int q = 0; q < 8; ++q) { w[q] = p[q]; p[q] = n[q]; }
    }

    float bb = B[c];
#pragma unroll
    for (int r = 0; r < 16; ++r) {
        C[(row0 + h * 16 + r) * 128 + c] = acc[r] + bb;
    }
}

// ---------------------------------------------------------------------------
// Small GEMM: C[N x 4] = act(A[N x 128] @ W[128 x 4] + b).
// ---------------------------------------------------------------------------
template <bool RELU>
__global__ void __launch_bounds__(128) gemm4_k(const float* __restrict__ Ap, int aid,
                                               const float* __restrict__ W,
                                               const float* __restrict__ B,
                                               float* __restrict__ Cp, int cid) {
    const float* __restrict__ A = resolve_c(Ap, aid);
    float* __restrict__ C = resolve_w(Cp, cid);

    __shared__ float As[32][132];
    const int t = threadIdx.x;
    const int row0 = blockIdx.x * 32;

    for (int i = t; i < 32 * 128; i += 128) As[i >> 7][i & 127] = A[row0 * 128 + i];
    __syncthreads();

    const int r = t >> 2, c = t & 3;
    float acc = 0.f;
#pragma unroll 8
    for (int k = 0; k < 128; ++k) acc = fmaf(As[r][k], W[k * 4 + c], acc);

    float v = acc + B[c];
    if (RELU) v = fmaxf(v, 0.f);
    C[(row0 + r) * 4 + c] = v;
}

// ---------------------------------------------------------------------------
// kNN v4: warp-per-row, register-distributed top-40 (lane l: slot0 all lanes,
// slot1 lanes 0..7). Hot loop processes 128 j per ballot: each lane computes
// 4 distances (conflict-free lane-strided LDS.128), mins them, ONE ballot.
// Candidate path (rare) re-ballots per 32-j sub-chunk; inserts use
// redux.sync.max.u32 on flipped-float keys. Threshold shrinks monotonically,
// so late re-filtering against the updated threshold is exact.
// ---------------------------------------------------------------------------
__global__ void __launch_bounds__(256) knn_k() {
    const float* __restrict__ S = g_s;
    int* __restrict__ IDX = g_idx;
    float* __restrict__ WW = g_w;

    constexpr int TJ = 512;
    __shared__ float4 sj[TJ];
    __shared__ float  s2j[TJ];

    const int t = threadIdx.x;
    const int lane = t & 31;
    const int wrp = t >> 5;                 // 8 warps = 8 rows per block
    const int row = blockIdx.x * 8 + wrp;

    const float4 si = reinterpret_cast<const float4*>(S)[row];
    float s2i = si.x * si.x;
    s2i = fmaf(si.y, si.y, s2i);
    s2i = fmaf(si.z, si.z, s2i);
    s2i = fmaf(si.w, si.w, s2i);

    const float INFP = __int_as_float(0x7f800000);
    const float INFN = __int_as_float(0xff800000);

    float bd0 = INFP;
    float bd1 = (lane < 8) ? INFP : INFN;   // -inf sentinel: never argmax
    int bi0 = 0, bi1 = 0;
    float worstAdj = INFP;                  // worst - s2i (warp-uniform)

    for (int base = 0; base < NN; base += TJ) {
        __syncthreads();
        for (int i = t; i < TJ; i += 256) {
            float4 v = reinterpret_cast<const float4*>(S)[base + i];
            float s2 = v.x * v.x;
            s2 = fmaf(v.y, v.y, s2);
            s2 = fmaf(v.z, v.z, s2);
            s2 = fmaf(v.w, v.w, s2);
            sj[i] = v;
            s2j[i] = s2;
        }
        __syncthreads();

        for (int stp = 0; stp < TJ; stp += 128) {
            float tv[4];
#pragma unroll
            for (int c2 = 0; c2 < 4; ++c2) {
                const int jj = stp + c2 * 32 + lane;
                float4 vj = sj[jj];
                float dot = si.x * vj.x;
                dot = fmaf(si.y, vj.y, dot);
                dot = fmaf(si.z, vj.z, dot);
                dot = fmaf(si.w, vj.w, dot);
                tv[c2] = fmaf(-2.f, dot, s2j[jj]);   // d - s2i
            }
            float tmin = fminf(fminf(tv[0], tv[1]), fminf(tv[2], tv[3]));
            if (!__ballot_sync(FULLMASK, tmin < worstAdj)) continue;

#pragma unroll
            for (int c2 = 0; c2 < 4; ++c2) {
                unsigned mask = __ballot_sync(FULLMASK, tv[c2] < worstAdj);
                while (mask) {
                    int src = __ffs(mask) - 1;
                    mask &= mask - 1;
                    float tc = __shfl_sync(FULLMASK, tv[c2], src);
                    if (tc < worstAdj) {
                        float dc = tc + s2i;
                        int jc = base + stp + c2 * 32 + src;
                        // replace current warp-max slot (redux argmax on keys)
                        unsigned mk = fkey(fmaxf(bd0, bd1));
                        unsigned bmax = __reduce_max_sync(FULLMASK, mk);
                        unsigned sel = __ballot_sync(FULLMASK, mk == bmax);
                        if (lane == __ffs(sel) - 1) {
                            if (bd0 >= bd1) { bd0 = dc; bi0 = jc; }
                            else            { bd1 = dc; bi1 = jc; }
                        }
                        // new threshold
                        mk = fkey(fmaxf(bd0, bd1));
                        bmax = __reduce_max_sync(FULLMASK, mk);
                        worstAdj = unfkey(bmax) - s2i;
                    }
                }
            }
        }
    }

    // write out the 40 slots (aggregation is order-invariant)
    IDX[row * KNB + lane] = bi0;
    WW[row * KNB + lane] = expf(-10.f * fmaxf(bd0, 0.f));
    if (lane < 8) {
        IDX[row * KNB + 32 + lane] = bi1;
        WW[row * KNB + 32 + lane] = expf(-10.f * fmaxf(bd1, 0.f));
    }
}

// ---------------------------------------------------------------------------
// Aggregation: g_agg[i] = [mean_k(g_h[idx_k] * w_k), max_k(g_h[idx_k] * w_k)]
// ---------------------------------------------------------------------------
__global__ void __launch_bounds__(256) agg_k() {
    const float* __restrict__ H = g_h;
    const int* __restrict__ IDX = g_idx;
    const float* __restrict__ WW = g_w;
    float* __restrict__ AGG = g_agg;

    __shared__ int   sidx[4][KNB];
    __shared__ float sw[4][KNB];
    const int t = threadIdx.x;
    const int r = t >> 6;
    const int d = t & 63;
    const int row = blockIdx.x * 4 + r;

    if (d < KNB) {
        sidx[r][d] = IDX[row * KNB + d];
        sw[r][d] = WW[row * KNB + d];
    }
    __syncthreads();

    float sum = 0.f, mx = -3.4e38f;
#pragma unroll 4
    for (int k = 0; k < KNB; ++k) {
        int j = sidx[r][k];
        float v = H[j * PROP + d] * sw[r][k];
        sum += v;
        mx = fmaxf(mx, v);
    }
    AGG[row * HID + d]      = sum * (1.f / 40.f);
    AGG[row * HID + 64 + d] = mx;
}

// ---------------------------------------------------------------------------
// Host: full pipeline as a chain of kernel launches (graph-capturable).
// ---------------------------------------------------------------------------
extern "C" void kernel_launch(void* const* d_in, const int* in_sizes, int n_in,
                              void* d_out, int out_size) {
    const float* x_in  = (const float*)d_in[0];
    const float* fc1_W = (const float*)d_in[1];
    const float* fc1_b = (const float*)d_in[2];
    const float* fc2_W = (const float*)d_in[3];
    const float* fc2_b = (const float*)d_in[4];
    const float* gs_W  = (const float*)d_in[5];
    const float* gs_b  = (const float*)d_in[6];
    const float* gh_W  = (const float*)d_in[7];
    const float* gh_b  = (const float*)d_in[8];
    const float* go_W  = (const float*)d_in[9];
    const float* go_b  = (const float*)d_in[10];
    const float* d1_W  = (const float*)d_in[11];
    const float* d1_b  = (const float*)d_in[12];
    const float* d2_W  = (const float*)d_in[13];
    const float* d2_b  = (const float*)d_in[14];
    const float* d3_W  = (const float*)d_in[15];
    const float* d3_b  = (const float*)d_in[16];
    const float* fc3_W = (const float*)d_in[17];
    const float* fc3_b = (const float*)d_in[18];
    const float* fc4_W = (const float*)d_in[19];
    const float* fc4_b = (const float*)d_in[20];
    float* out = (float*)d_out;

    const int GB = NN / 32;  // 512 blocks

    // fc1: x_in -> g_x(relu), fc2: g_x -> g_y(relu)
    gemm_k<9, 128, true><<<GB, 256>>>(x_in, -1, fc1_W, fc1_b, nullptr, 0);
    gemm_k<128, 128, true><<<GB, 256>>>(nullptr, 0, fc2_W, fc2_b, nullptr, 1);

    // x lives in g_y across layers; g_x is the ping-pong scratch.
    for (int i = 0; i < NLAYERS; ++i) {
        gemm4_k<false><<<GB, 128>>>(nullptr, 1, gs_W + i * HID * SPACE, gs_b + i * SPACE, nullptr, 4);
        gemm_k<128, 64, false><<<GB, 256>>>(nullptr, 1, gh_W + i * HID * PROP, gh_b + i * PROP, nullptr, 3);
        knn_k<<<NN / 8, 256>>>();
        agg_k<<<NN / 4, 256>>>();
        gemm2_k<<<GB, 256>>>(go_W + i * 2 * HID * HID, go_b + i * HID);  // [g_y|g_agg] -> g_x
        gemm_k<128, 128, true><<<GB, 256>>>(nullptr, 0, d1_W + i * HID * HID, d1_b + i * HID, nullptr, 1);
        gemm_k<128, 128, true><<<GB, 256>>>(nullptr, 1, d2_W + i * HID * HID, d2_b + i * HID, nullptr, 0);
        gemm_k<128, 128, true><<<GB, 256>>>(nullptr, 0, d3_W + i * HID * HID, d3_b + i * HID, nullptr, 1);
    }

    // fc3: g_y -> g_x(relu), fc4: g_x -> out
    gemm_k<128, 128, true><<<GB, 256>>>(nullptr, 1, fc3_W, fc3_b, nullptr, 0);
    gemm4_k<false><<<GB, 128>>>(nullptr, 0, fc4_W, fc4_b, out, -1);
}

// round 11
// speedup vs baseline: 1.0756x; 1.0756x over previous
#include <cuda_runtime.h>
#include <math.h>

// Problem constants
#define NN   16384
#define HID  128
#define PROP 64
#define SPACE 4
#define KNB  40
#define NLAYERS 4
#define FULLMASK 0xFFFFFFFFu

// Scratch (static device allocations; no cudaMalloc allowed)
__device__ float g_x[NN * HID];
__device__ float g_y[NN * HID];
__device__ float g_s[NN * SPACE];
__device__ float g_h[NN * PROP];
__device__ float g_agg[NN * HID];
__device__ float g_w[NN * KNB];
__device__ int   g_idx[NN * KNB];

// Device-side buffer resolution: keeps kernel_launch free of any host API
// besides kernel launches. ids: 0=g_x, 1=g_y, 2=g_agg, 3=g_h, 4=g_s, -1=arg.
__device__ __forceinline__ const float* resolve_c(const float* p, int id) {
    switch (id) {
        case 0: return g_x;
        case 1: return g_y;
        case 2: return g_agg;
        case 3: return g_h;
        case 4: return g_s;
        default: return p;
    }
}
__device__ __forceinline__ float* resolve_w(float* p, int id) {
    switch (id) {
        case 0: return g_x;
        case 1: return g_y;
        case 2: return g_agg;
        case 3: return g_h;
        case 4: return g_s;
        default: return p;
    }
}

// Monotone float <-> uint key maps (for redux.max over distances).
__device__ __forceinline__ unsigned fkey(float f) {
    unsigned u = __float_as_uint(f);
    return u ^ ((unsigned)((int)u >> 31) | 0x80000000u);
}
__device__ __forceinline__ float unfkey(unsigned k) {
    unsigned m = (k & 0x80000000u) ? 0x80000000u : 0xFFFFFFFFu;
    return __uint_as_float(k ^ m);
}

// ---------------------------------------------------------------------------
// Tiled SGEMM: C[N x MD] = act(A[N x KD] @ W[KD x MD] + b)
// 256 threads: thread (c = t%MD, h = t/MD) owns column c for RPT=MD/8 rows.
// W consumed in chunks of 8 with double buffering and POINTER-INCREMENT
// addressing: LDG/LDS at immediate offsets, one IADD per chunk (kills the
// IMAD/LEA address-ALU overhead ncu showed at 13.3% of issue).
// ---------------------------------------------------------------------------
template <int KD, int MD, bool RELU>
__global__ void __launch_bounds__(256) gemm_k(const float* __restrict__ Ap, int aid,
                                              const float* __restrict__ W,
                                              const float* __restrict__ B,
                                              float* __restrict__ Cp, int cid) {
    constexpr int RPT = MD / 8;  // rows per thread (MD=128 -> 16, MD=64 -> 8)
    const float* __restrict__ A = resolve_c(Ap, aid);
    float* __restrict__ C = resolve_w(Cp, cid);

    __shared__ float As[32 * KD];
    const int t = threadIdx.x;
    const int c = t % MD;
    const int h = t / MD;
    const int row0 = blockIdx.x * 32;

    {
        const float4* src = reinterpret_cast<const float4*>(A + row0 * KD);
        float4* dst = reinterpret_cast<float4*>(As);
        for (int i = t; i < 8 * KD; i += 256) dst[i] = src[i];
    }
    __syncthreads();

    float acc[RPT];
#pragma unroll
    for (int r = 0; r < RPT; ++r) acc[r] = 0.f;

    const float* Asb = As + (h * RPT) * KD;

    if constexpr (KD % 16 == 0) {
        constexpr int NCH = KD / 8;  // even number of 8-wide chunks
        const float* Wp = W + c;
        const float* Asp = Asb;
        float wb[8], wn[8];
#pragma unroll
        for (int q = 0; q < 8; ++q) wb[q] = Wp[q * MD];
        Wp += 8 * MD;

        for (int kb = 0; kb < NCH; kb += 2) {
            // prefetch chunk kb+1 (always valid: NCH even)
#pragma unroll
            for (int q = 0; q < 8; ++q) wn[q] = Wp[q * MD];
            Wp += 8 * MD;
            // compute chunk kb with wb
#pragma unroll
            for (int r = 0; r < RPT; ++r) {
                float4 a0 = *reinterpret_cast<const float4*>(&Asp[r * KD + 0]);
                float4 a1 = *reinterpret_cast<const float4*>(&Asp[r * KD + 4]);
                float v = acc[r];
                v = fmaf(a0.x, wb[0], v);
                v = fmaf(a0.y, wb[1], v);
                v = fmaf(a0.z, wb[2], v);
                v = fmaf(a0.w, wb[3], v);
                v = fmaf(a1.x, wb[4], v);
                v = fmaf(a1.y, wb[5], v);
                v = fmaf(a1.z, wb[6], v);
                v = fmaf(a1.w, wb[7], v);
                acc[r] = v;
            }
            Asp += 8;
            // prefetch chunk kb+2 into wb (if valid)
            if (kb + 2 < NCH) {
#pragma unroll
                for (int q = 0; q < 8; ++q) wb[q] = Wp[q * MD];
                Wp += 8 * MD;
            }
            // compute chunk kb+1 with wn
#pragma unroll
            for (int r = 0; r < RPT; ++r) {
                float4 a0 = *reinterpret_cast<const float4*>(&Asp[r * KD + 0]);
                float4 a1 = *reinterpret_cast<const float4*>(&Asp[r * KD + 4]);
                float v = acc[r];
                v = fmaf(a0.x, wn[0], v);
                v = fmaf(a0.y, wn[1], v);
                v = fmaf(a0.z, wn[2], v);
                v = fmaf(a0.w, wn[3], v);
                v = fmaf(a1.x, wn[4], v);
                v = fmaf(a1.y, wn[5], v);
                v = fmaf(a1.z, wn[6], v);
                v = fmaf(a1.w, wn[7], v);
                acc[r] = v;
            }
            Asp += 8;
        }
    } else {
        for (int k = 0; k < KD; ++k) {
            float wv = W[k * MD + c];
#pragma unroll
            for (int r = 0; r < RPT; ++r) acc[r] = fmaf(Asb[r * KD + k], wv, acc[r]);
        }
    }

    float bb = B[c];
#pragma unroll
    for (int r = 0; r < RPT; ++r) {
        float v = acc[r] + bb;
        if (RELU) v = fmaxf(v, 0.f);
        C[(row0 + h * RPT + r) * MD + c] = v;
    }
}

// ---------------------------------------------------------------------------
// Two-source SGEMM for lin_out: g_x = [g_y | g_agg] @ W + b, KD=256, MD=128.
// Same pointer-increment chunked scheme.
// ---------------------------------------------------------------------------
__global__ void __launch_bounds__(256) gemm2_k(const float* __restrict__ W,
                                               const float* __restrict__ B) {
    const float* __restrict__ A1 = g_y;
    const float* __restrict__ A2 = g_agg;
    float* __restrict__ C = g_x;

    __shared__ float As[32 * 256];
    const int t = threadIdx.x;
    const int c = t % 128;
    const int h = t / 128;
    const int row0 = blockIdx.x * 32;

    {
        const float4* s1 = reinterpret_cast<const float4*>(A1 + row0 * 128);
        const float4* s2 = reinterpret_cast<const float4*>(A2 + row0 * 128);
        float4* dst = reinterpret_cast<float4*>(As);
        for (int i = t; i < 32 * 32; i += 256) {
            int r = i >> 5, kq = i & 31;
            dst[r * 64 + kq]      = s1[r * 32 + kq];
            dst[r * 64 + 32 + kq] = s2[r * 32 + kq];
        }
    }
    __syncthreads();

    float acc[16];
#pragma unroll
    for (int r = 0; r < 16; ++r) acc[r] = 0.f;

    constexpr int KD = 256;
    constexpr int NCH = KD / 8;  // 32 chunks
    const float* Wp = W + c;
    const float* Asp = As + (h * 16) * KD;
    float wb[8], wn[8];
#pragma unroll
    for (int q = 0; q < 8; ++q) wb[q] = Wp[q * 128];
    Wp += 8 * 128;

    for (int kb = 0; kb < NCH; kb += 2) {
#pragma unroll
        for (int q = 0; q < 8; ++q) wn[q] = Wp[q * 128];
        Wp += 8 * 128;
#pragma unroll
        for (int r = 0; r < 16; ++r) {
            float4 a0 = *reinterpret_cast<const float4*>(&Asp[r * KD + 0]);
            float4 a1 = *reinterpret_cast<const float4*>(&Asp[r * KD + 4]);
            float v = acc[r];
            v = fmaf(a0.x, wb[0], v);
            v = fmaf(a0.y, wb[1], v);
            v = fmaf(a0.z, wb[2], v);
            v = fmaf(a0.w, wb[3], v);
            v = fmaf(a1.x, wb[4], v);
            v = fmaf(a1.y, wb[5], v);
            v = fmaf(a1.z, wb[6], v);
            v = fmaf(a1.w, wb[7], v);
            acc[r] = v;
        }
        Asp += 8;
        if (kb + 2 < NCH) {
#pragma unroll
            for (int q = 0; q < 8; ++q) wb[q] = Wp[q * 128];
            Wp += 8 * 128;
        }
#pragma unroll
        for (int r = 0; r < 16; ++r) {
            float4 a0 = *reinterpret_cast<const float4*>(&Asp[r * KD + 0]);
            float4 a1 = *reinterpret_cast<const float4*>(&Asp[r * KD + 4]);
            float v = acc[r];
            v = fmaf(a0.x, wn[0], v);
            v = fmaf(a0.y, wn[1], v);
            v = fmaf(a0.z, wn[2], v);
            v = fmaf(a0.w, wn[3], v);
            v = fmaf(a1.x, wn[4], v);
            v = fmaf(a1.y, wn[5], v);
            v = fmaf(a1.z, wn[6], v);
            v = fmaf(a1.w, wn[7], v);
            acc[r] = v;
        }
        Asp += 8;
    }

    float bb = B[c];
#pragma unroll
    for (int r = 0; r < 16; ++r) {
        C[(row0 + h * 16 + r) * 128 + c] = acc[r] + bb;
    }
}

// ---------------------------------------------------------------------------
// Small GEMM: C[N x 4] = act(A[N x 128] @ W[128 x 4] + b).
// ---------------------------------------------------------------------------
template <bool RELU>
__global__ void __launch_bounds__(128) gemm4_k(const float* __restrict__ Ap, int aid,
                                               const float* __restrict__ W,
                                               const float* __restrict__ B,
                                               float* __restrict__ Cp, int cid) {
    const float* __restrict__ A = resolve_c(Ap, aid);
    float* __restrict__ C = resolve_w(Cp, cid);

    __shared__ float As[32][132];
    const int t = threadIdx.x;
    const int row0 = blockIdx.x * 32;

    for (int i = t; i < 32 * 128; i += 128) As[i >> 7][i & 127] = A[row0 * 128 + i];
    __syncthreads();

    const int r = t >> 2, c = t & 3;
    float acc = 0.f;
#pragma unroll 8
    for (int k = 0; k < 128; ++k) acc = fmaf(As[r][k], W[k * 4 + c], acc);

    float v = acc + B[c];
    if (RELU) v = fmaxf(v, 0.f);
    C[(row0 + r) * 4 + c] = v;
}

// ---------------------------------------------------------------------------
// kNN v5: warp-per-row, register-distributed top-40 (lane l: slot0 all lanes,
// slot1 lanes 0..7). Hot loop = Round-8 form (32 j per ballot, known-good).
// Insert path halved: each lane tracks its slot-max key (mymk); the threshold
// REDUX from insert i doubles as the argmax key for insert i+1 (buffer is
// unchanged between inserts), so insert = ballot(mymk==bmaxKey) + replace +
// ONE redux, exactly.
// ---------------------------------------------------------------------------
__global__ void __launch_bounds__(256) knn_k() {
    const float* __restrict__ S = g_s;
    int* __restrict__ IDX = g_idx;
    float* __restrict__ WW = g_w;

    constexpr int TJ = 512;
    __shared__ float4 sj[TJ];
    __shared__ float  s2j[TJ];

    const int t = threadIdx.x;
    const int lane = t & 31;
    const int wrp = t >> 5;                 // 8 warps = 8 rows per block
    const int row = blockIdx.x * 8 + wrp;

    const float4 si = reinterpret_cast<const float4*>(S)[row];
    float s2i = si.x * si.x;
    s2i = fmaf(si.y, si.y, s2i);
    s2i = fmaf(si.z, si.z, s2i);
    s2i = fmaf(si.w, si.w, s2i);

    const float INFP = __int_as_float(0x7f800000);
    const float INFN = __int_as_float(0xff800000);

    float bd0 = INFP;
    float bd1 = (lane < 8) ? INFP : INFN;   // -inf sentinel: never argmax
    int bi0 = 0, bi1 = 0;
    unsigned mymk = fkey(INFP);             // per-lane max key over its slots
    unsigned bmaxKey = mymk;                // warp-uniform cached argmax key
    float worstAdj = INFP;                  // worst - s2i (warp-uniform)

    for (int base = 0; base < NN; base += TJ) {
        __syncthreads();
        for (int i = t; i < TJ; i += 256) {
            float4 v = reinterpret_cast<const float4*>(S)[base + i];
            float s2 = v.x * v.x;
            s2 = fmaf(v.y, v.y, s2);
            s2 = fmaf(v.z, v.z, s2);
            s2 = fmaf(v.w, v.w, s2);
            sj[i] = v;
            s2j[i] = s2;
        }
        __syncthreads();

#pragma unroll 2
        for (int stp = 0; stp < TJ; stp += 32) {
            float4 vj = sj[stp + lane];
            float dot = si.x * vj.x;
            dot = fmaf(si.y, vj.y, dot);
            dot = fmaf(si.z, vj.z, dot);
            dot = fmaf(si.w, vj.w, dot);
            float tval = fmaf(-2.f, dot, s2j[stp + lane]);  // d - s2i

            unsigned mask = __ballot_sync(FULLMASK, tval < worstAdj);
            while (mask) {
                int src = __ffs(mask) - 1;
                mask &= mask - 1;
                float tc = __shfl_sync(FULLMASK, tval, src);
                if (tc < worstAdj) {
                    float dc = tc + s2i;
                    int jc = base + stp + src;
                    // locate a max slot using the CACHED key (no argmax redux)
                    unsigned sel = __ballot_sync(FULLMASK, mymk == bmaxKey);
                    if (lane == __ffs(sel) - 1) {
                        if (bd0 >= bd1) { bd0 = dc; bi0 = jc; }
                        else            { bd1 = dc; bi1 = jc; }
                        mymk = fkey(fmaxf(bd0, bd1));
                    }
                    // single redux: new threshold AND next insert's argmax key
                    bmaxKey = __reduce_max_sync(FULLMASK, mymk);
                    worstAdj = unfkey(bmaxKey) - s2i;
                }
            }
        }
    }

    // write out the 40 slots (aggregation is order-invariant)
    IDX[row * KNB + lane] = bi0;
    WW[row * KNB + lane] = expf(-10.f * fmaxf(bd0, 0.f));
    if (lane < 8) {
        IDX[row * KNB + 32 + lane] = bi1;
        WW[row * KNB + 32 + lane] = expf(-10.f * fmaxf(bd1, 0.f));
    }
}

// ---------------------------------------------------------------------------
// Aggregation: g_agg[i] = [mean_k(g_h[idx_k] * w_k), max_k(g_h[idx_k] * w_k)]
// ---------------------------------------------------------------------------
__global__ void __launch_bounds__(256) agg_k() {
    const float* __restrict__ H = g_h;
    const int* __restrict__ IDX = g_idx;
    const float* __restrict__ WW = g_w;
    float* __restrict__ AGG = g_agg;

    __shared__ int   sidx[4][KNB];
    __shared__ float sw[4][KNB];
    const int t = threadIdx.x;
    const int r = t >> 6;
    const int d = t & 63;
    const int row = blockIdx.x * 4 + r;

    if (d < KNB) {
        sidx[r][d] = IDX[row * KNB + d];
        sw[r][d] = WW[row * KNB + d];
    }
    __syncthreads();

    float sum = 0.f, mx = -3.4e38f;
#pragma unroll 4
    for (int k = 0; k < KNB; ++k) {
        int j = sidx[r][k];
        float v = H[j * PROP + d] * sw[r][k];
        sum += v;
        mx = fmaxf(mx, v);
    }
    AGG[row * HID + d]      = sum * (1.f / 40.f);
    AGG[row * HID + 64 + d] = mx;
}

// ---------------------------------------------------------------------------
// Host: full pipeline as a chain of kernel launches (graph-capturable).
// ---------------------------------------------------------------------------
extern "C" void kernel_launch(void* const* d_in, const int* in_sizes, int n_in,
                              void* d_out, int out_size) {
    const float* x_in  = (const float*)d_in[0];
    const float* fc1_W = (const float*)d_in[1];
    const float* fc1_b = (const float*)d_in[2];
    const float* fc2_W = (const float*)d_in[3];
    const float* fc2_b = (const float*)d_in[4];
    const float* gs_W  = (const float*)d_in[5];
    const float* gs_b  = (const float*)d_in[6];
    const float* gh_W  = (const float*)d_in[7];
    const float* gh_b  = (const float*)d_in[8];
    const float* go_W  = (const float*)d_in[9];
    const float* go_b  = (const float*)d_in[10];
    const float* d1_W  = (const float*)d_in[11];
    const float* d1_b  = (const float*)d_in[12];
    const float* d2_W  = (const float*)d_in[13];
    const float* d2_b  = (const float*)d_in[14];
    const float* d3_W  = (const float*)d_in[15];
    const float* d3_b  = (const float*)d_in[16];
    const float* fc3_W = (const float*)d_in[17];
    const float* fc3_b = (const float*)d_in[18];
    const float* fc4_W = (const float*)d_in[19];
    const float* fc4_b = (const float*)d_in[20];
    float* out = (float*)d_out;

    const int GB = NN / 32;  // 512 blocks

    // fc1: x_in -> g_x(relu), fc2: g_x -> g_y(relu)
    gemm_k<9, 128, true><<<GB, 256>>>(x_in, -1, fc1_W, fc1_b, nullptr, 0);
    gemm_k<128, 128, true><<<GB, 256>>>(nullptr, 0, fc2_W, fc2_b, nullptr, 1);

    // x lives in g_y across layers; g_x is the ping-pong scratch.
    for (int i = 0; i < NLAYERS; ++i) {
        gemm4_k<false><<<GB, 128>>>(nullptr, 1, gs_W + i * HID * SPACE, gs_b + i * SPACE, nullptr, 4);
        gemm_k<128, 64, false><<<GB, 256>>>(nullptr, 1, gh_W + i * HID * PROP, gh_b + i * PROP, nullptr, 3);
        knn_k<<<NN / 8, 256>>>();
        agg_k<<<NN / 4, 256>>>();
        gemm2_k<<<GB, 256>>>(go_W + i * 2 * HID * HID, go_b + i * HID);  // [g_y|g_agg] -> g_x
        gemm_k<128, 128, true><<<GB, 256>>>(nullptr, 0, d1_W + i * HID * HID, d1_b + i * HID, nullptr, 1);
        gemm_k<128, 128, true><<<GB, 256>>>(nullptr, 1, d2_W + i * HID * HID, d2_b + i * HID, nullptr, 0);
        gemm_k<128, 128, true><<<GB, 256>>>(nullptr, 0, d3_W + i * HID * HID, d3_b + i * HID, nullptr, 1);
    }

    // fc3: g_y -> g_x(relu), fc4: g_x -> out
    gemm_k<128, 128, true><<<GB, 256>>>(nullptr, 1, fc3_W, fc3_b, nullptr, 0);
    gemm4_k<false><<<GB, 128>>>(nullptr, 0, fc4_W, fc4_b, out, -1);
}

// round 14
// speedup vs baseline: 1.1162x; 1.0377x over previous
#include <cuda_runtime.h>
#include <cuda_bf16.h>
#include <math.h>
#include <cstdint>

// Problem constants
#define NN   16384
#define HID  128
#define PROP 64
#define SPACE 4
#define KNB  40
#define NLAYERS 4
#define FULLMASK 0xFFFFFFFFu

// Scratch (static device allocations; no cudaMalloc allowed)
__device__ float g_x[NN * HID];
__device__ float g_y[NN * HID];
__device__ float g_s[NN * SPACE];
__device__ float g_h[NN * PROP];
__device__ float g_agg[NN * HID];
__device__ float g_w[NN * KNB];
__device__ int   g_idx[NN * KNB];

// ids: 0=g_x, 1=g_y, 2=g_agg, 3=g_h, 4=g_s, -1=arg.
__device__ __forceinline__ const float* resolve_c(const float* p, int id) {
    switch (id) {
        case 0: return g_x;
        case 1: return g_y;
        case 2: return g_agg;
        case 3: return g_h;
        case 4: return g_s;
        default: return p;
    }
}
__device__ __forceinline__ float* resolve_w(float* p, int id) {
    switch (id) {
        case 0: return g_x;
        case 1: return g_y;
        case 2: return g_agg;
        case 3: return g_h;
        case 4: return g_s;
        default: return p;
    }
}

// Monotone float <-> uint key maps (for redux.max over distances).
__device__ __forceinline__ unsigned fkey(float f) {
    unsigned u = __float_as_uint(f);
    return u ^ ((unsigned)((int)u >> 31) | 0x80000000u);
}
__device__ __forceinline__ float unfkey(unsigned k) {
    unsigned m = (k & 0x80000000u) ? 0x80000000u : 0xFFFFFFFFu;
    return __uint_as_float(k ^ m);
}

__device__ __forceinline__ unsigned packbf(__nv_bfloat16 a, __nv_bfloat16 b) {
    return (unsigned)__bfloat16_as_ushort(a) | ((unsigned)__bfloat16_as_ushort(b) << 16);
}
// split float into bf16 hi + bf16 lo (residual)
__device__ __forceinline__ void bfsplit(float f, __nv_bfloat16& h, __nv_bfloat16& l) {
    h = __float2bfloat16_rn(f);
    l = __float2bfloat16_rn(f - __bfloat162float(h));
}

__device__ __forceinline__ void mma16816(float* c, const uint32_t* a,
                                         uint32_t b0, uint32_t b1) {
    asm volatile(
        "mma.sync.aligned.m16n8k16.row.col.f32.bf16.bf16.f32 "
        "{%0,%1,%2,%3}, {%4,%5,%6,%7}, {%8,%9}, {%0,%1,%2,%3};"
        : "+f"(c[0]), "+f"(c[1]), "+f"(c[2]), "+f"(c[3])
        : "r"(a[0]), "r"(a[1]), "r"(a[2]), "r"(a[3]), "r"(b0), "r"(b1));
}

// ===========================================================================
// Tensor-core GEMM via mma.sync (base-ISA, works at compute_103):
// C[N x MD] = act(A[N x KD] @ W[KD x MD] + b)
// Grid = 128 CTAs x 256 threads. CTA tile: 128 rows x MD cols. 8 warps, each
// owns a 16-row stripe and ALL MD columns (acc in registers).
// K in chunks of 16: A and W converted to bf16 hi/lo packed-pair tiles in
// shared; 3 mma products per (nc, kc): AhBh + AhBl + AlBh (AlBl ~2^-16, drop).
// ===========================================================================
template <int KD, int MD, bool RELU, bool TWOSRC>
__global__ void __launch_bounds__(256) mmagemm_k(const float* __restrict__ Ap, int aid,
                                                 const float* __restrict__ W,
                                                 const float* __restrict__ B,
                                                 float* __restrict__ Cp, int cid) {
    constexpr int NC = MD / 8;    // n-chunks per warp
    constexpr int KC = KD / 16;   // k-chunks
    const float* __restrict__ A = resolve_c(Ap, aid);
    float* __restrict__ C = resolve_w(Cp, cid);

    // packed bf16-pair tiles, pad to 9 words/row to de-bank LDS
    __shared__ uint32_t sAh[128][9], sAl[128][9];
    __shared__ uint32_t sBh[MD][9], sBl[MD][9];
    __shared__ float sBias[MD];

    const int t = threadIdx.x;
    const int warp = t >> 5;
    const int lane = t & 31;
    const int g = lane >> 2;      // group id (row within fragment)
    const int t4 = lane & 3;      // thread-in-group
    const int row0 = blockIdx.x * 128;

    if (t < MD) sBias[t] = B[t];

    float acc[NC][4];
#pragma unroll
    for (int nc = 0; nc < NC; ++nc)
#pragma unroll
        for (int q = 0; q < 4; ++q) acc[nc][q] = 0.f;

    for (int kc = 0; kc < KC; ++kc) {
        const int k0 = kc * 16;
        __syncthreads();  // prior-phase fragment reads done before overwrite

        // ---- stage A: rows 0..127, k0..k0+15 -> sAh/sAl packed pairs ----
        {
            const int r = t >> 1;           // 0..127
            const int hf = t & 1;           // k half: 0 -> k0..k0+7, 1 -> +8
            const int kk = k0 + hf * 8;
            const float* src;
            if (TWOSRC) {  // KD=256: cols 0-127 g_y, 128-255 g_agg
                src = (kk < 128) ? &g_y[(row0 + r) * 128 + kk]
                                 : &g_agg[(row0 + r) * 128 + (kk - 128)];
            } else {
                src = &A[(row0 + r) * KD + kk];
            }
            float4 v0 = reinterpret_cast<const float4*>(src)[0];
            float4 v1 = reinterpret_cast<const float4*>(src)[1];
            float f[8] = {v0.x, v0.y, v0.z, v0.w, v1.x, v1.y, v1.z, v1.w};
#pragma unroll
            for (int j = 0; j < 4; ++j) {
                __nv_bfloat16 h0, l0, h1, l1;
                bfsplit(f[2 * j], h0, l0);
                bfsplit(f[2 * j + 1], h1, l1);
                sAh[r][hf * 4 + j] = packbf(h0, h1);
                sAl[r][hf * 4 + j] = packbf(l0, l1);
            }
        }
        // ---- stage B: W[k0..k0+15][0..MD) -> sBh/sBl [n][q], q = k-pair ----
        {
            for (int e = t; e < MD * 8; e += 256) {
                const int n = e % MD;
                const int q = e / MD;       // 0..7
                float f0 = W[(k0 + 2 * q) * MD + n];
                float f1 = W[(k0 + 2 * q + 1) * MD + n];
                __nv_bfloat16 h0, l0, h1, l1;
                bfsplit(f0, h0, l0);
                bfsplit(f1, h1, l1);
                sBh[n][q] = packbf(h0, h1);
                sBl[n][q] = packbf(l0, l1);
            }
        }
        __syncthreads();

        // ---- A fragments for this warp's 16-row stripe ----
        const int ar0 = warp * 16 + g;
        const int ar1 = ar0 + 8;
        uint32_t ah[4] = {sAh[ar0][t4], sAh[ar1][t4], sAh[ar0][t4 + 4], sAh[ar1][t4 + 4]};
        uint32_t al[4] = {sAl[ar0][t4], sAl[ar1][t4], sAl[ar0][t4 + 4], sAl[ar1][t4 + 4]};

#pragma unroll
        for (int nc = 0; nc < NC; ++nc) {
            const int bn = nc * 8 + g;
            uint32_t bh0 = sBh[bn][t4], bh1 = sBh[bn][t4 + 4];
            uint32_t bl0 = sBl[bn][t4], bl1 = sBl[bn][t4 + 4];
            mma16816(acc[nc], ah, bh0, bh1);
            mma16816(acc[nc], ah, bl0, bl1);
            mma16816(acc[nc], al, bh0, bh1);
        }
    }

    // ---- epilogue: bias + act, write two rows per lane ----
    const int r0 = row0 + warp * 16 + g;
#pragma unroll
    for (int nc = 0; nc < NC; ++nc) {
        const int c0 = nc * 8 + 2 * t4;
        float b0 = sBias[c0], b1 = sBias[c0 + 1];
        float2 o0, o1;
        o0.x = acc[nc][0] + b0; o0.y = acc[nc][1] + b1;
        o1.x = acc[nc][2] + b0; o1.y = acc[nc][3] + b1;
        if (RELU) {
            o0.x = fmaxf(o0.x, 0.f); o0.y = fmaxf(o0.y, 0.f);
            o1.x = fmaxf(o1.x, 0.f); o1.y = fmaxf(o1.y, 0.f);
        }
        *reinterpret_cast<float2*>(&C[r0 * MD + c0]) = o0;
        *reinterpret_cast<float2*>(&C[(r0 + 8) * MD + c0]) = o1;
    }
}

// ---------------------------------------------------------------------------
// SIMT SGEMM kept only for fc1 (KD=9).
// ---------------------------------------------------------------------------
template <int KD, int MD, bool RELU>
__global__ void __launch_bounds__(256) gemm_k(const float* __restrict__ Ap, int aid,
                                              const float* __restrict__ W,
                                              const float* __restrict__ B,
                                              float* __restrict__ Cp, int cid) {
    constexpr int RPT = MD / 8;
    const float* __restrict__ A = resolve_c(Ap, aid);
    float* __restrict__ C = resolve_w(Cp, cid);

    __shared__ float As[32 * KD];
    const int t = threadIdx.x;
    const int c = t % MD;
    const int h = t / MD;
    const int row0 = blockIdx.x * 32;

    for (int i = t; i < 32 * KD; i += 256) As[i] = A[row0 * KD + i];
    __syncthreads();

    float acc[RPT];
#pragma unroll
    for (int r = 0; r < RPT; ++r) acc[r] = 0.f;

    const float* Asb = As + (h * RPT) * KD;
    for (int k = 0; k < KD; ++k) {
        float wv = W[k * MD + c];
#pragma unroll
        for (int r = 0; r < RPT; ++r) acc[r] = fmaf(Asb[r * KD + k], wv, acc[r]);
    }

    float bb = B[c];
#pragma unroll
    for (int r = 0; r < RPT; ++r) {
        float v = acc[r] + bb;
        if (RELU) v = fmaxf(v, 0.f);
        C[(row0 + h * RPT + r) * MD + c] = v;
    }
}

// ---------------------------------------------------------------------------
// Small GEMM: C[N x 4] = act(A[N x 128] @ W[128 x 4] + b).
// ---------------------------------------------------------------------------
template <bool RELU>
__global__ void __launch_bounds__(128) gemm4_k(const float* __restrict__ Ap, int aid,
                                               const float* __restrict__ W,
                                               const float* __restrict__ B,
                                               float* __restrict__ Cp, int cid) {
    const float* __restrict__ A = resolve_c(Ap, aid);
    float* __restrict__ C = resolve_w(Cp, cid);

    __shared__ float As[32][132];
    const int t = threadIdx.x;
    const int row0 = blockIdx.x * 32;

    for (int i = t; i < 32 * 128; i += 128) As[i >> 7][i & 127] = A[row0 * 128 + i];
    __syncthreads();

    const int r = t >> 2, c = t & 3;
    float acc = 0.f;
#pragma unroll 8
    for (int k = 0; k < 128; ++k) acc = fmaf(As[r][k], W[k * 4 + c], acc);

    float v = acc + B[c];
    if (RELU) v = fmaxf(v, 0.f);
    C[(row0 + r) * 4 + c] = v;
}

// ---------------------------------------------------------------------------
// kNN (R11 known-good): warp-per-row, register-distributed top-40.
// ---------------------------------------------------------------------------
__global__ void __launch_bounds__(256) knn_k() {
    const float* __restrict__ S = g_s;
    int* __restrict__ IDX = g_idx;
    float* __restrict__ WW = g_w;

    constexpr int TJ = 512;
    __shared__ float4 sj[TJ];
    __shared__ float  s2j[TJ];

    const int t = threadIdx.x;
    const int lane = t & 31;
    const int wrp = t >> 5;
    const int row = blockIdx.x * 8 + wrp;

    const float4 si = reinterpret_cast<const float4*>(S)[row];
    float s2i = si.x * si.x;
    s2i = fmaf(si.y, si.y, s2i);
    s2i = fmaf(si.z, si.z, s2i);
    s2i = fmaf(si.w, si.w, s2i);

    const float INFP = __int_as_float(0x7f800000);
    const float INFN = __int_as_float(0xff800000);

    float bd0 = INFP;
    float bd1 = (lane < 8) ? INFP : INFN;
    int bi0 = 0, bi1 = 0;
    unsigned mymk = fkey(INFP);
    unsigned bmaxKey = mymk;
    float worstAdj = INFP;

    for (int base = 0; base < NN; base += TJ) {
        __syncthreads();
        for (int i = t; i < TJ; i += 256) {
            float4 v = reinterpret_cast<const float4*>(S)[base + i];
            float s2 = v.x * v.x;
            s2 = fmaf(v.y, v.y, s2);
            s2 = fmaf(v.z, v.z, s2);
            s2 = fmaf(v.w, v.w, s2);
            sj[i] = v;
            s2j[i] = s2;
        }
        __syncthreads();

#pragma unroll 2
        for (int stp = 0; stp < TJ; stp += 32) {
            float4 vj = sj[stp + lane];
            float dot = si.x * vj.x;
            dot = fmaf(si.y, vj.y, dot);
            dot = fmaf(si.z, vj.z, dot);
            dot = fmaf(si.w, vj.w, dot);
            float tval = fmaf(-2.f, dot, s2j[stp + lane]);

            unsigned mask = __ballot_sync(FULLMASK, tval < worstAdj);
            while (mask) {
                int src = __ffs(mask) - 1;
                mask &= mask - 1;
                float tc = __shfl_sync(FULLMASK, tval, src);
                if (tc < worstAdj) {
                    float dc = tc + s2i;
                    int jc = base + stp + src;
                    unsigned sel = __ballot_sync(FULLMASK, mymk == bmaxKey);
                    if (lane == __ffs(sel) - 1) {
                        if (bd0 >= bd1) { bd0 = dc; bi0 = jc; }
                        else            { bd1 = dc; bi1 = jc; }
                        mymk = fkey(fmaxf(bd0, bd1));
                    }
                    bmaxKey = __reduce_max_sync(FULLMASK, mymk);
                    worstAdj = unfkey(bmaxKey) - s2i;
                }
            }
        }
    }

    IDX[row * KNB + lane] = bi0;
    WW[row * KNB + lane] = expf(-10.f * fmaxf(bd0, 0.f));
    if (lane < 8) {
        IDX[row * KNB + 32 + lane] = bi1;
        WW[row * KNB + 32 + lane] = expf(-10.f * fmaxf(bd1, 0.f));
    }
}

// ---------------------------------------------------------------------------
// Aggregation: g_agg[i] = [mean_k(g_h[idx_k] * w_k), max_k(g_h[idx_k] * w_k)]
// ---------------------------------------------------------------------------
__global__ void __launch_bounds__(256) agg_k() {
    const float* __restrict__ H = g_h;
    const int* __restrict__ IDX = g_idx;
    const float* __restrict__ WW = g_w;
    float* __restrict__ AGG = g_agg;

    __shared__ int   sidx[4][KNB];
    __shared__ float sw[4][KNB];
    const int t = threadIdx.x;
    const int r = t >> 6;
    const int d = t & 63;
    const int row = blockIdx.x * 4 + r;

    if (d < KNB) {
        sidx[r][d] = IDX[row * KNB + d];
        sw[r][d] = WW[row * KNB + d];
    }
    __syncthreads();

    float sum = 0.f, mx = -3.4e38f;
#pragma unroll 4
    for (int k = 0; k < KNB; ++k) {
        int j = sidx[r][k];
        float v = H[j * PROP + d] * sw[r][k];
        sum += v;
        mx = fmaxf(mx, v);
    }
    AGG[row * HID + d]      = sum * (1.f / 40.f);
    AGG[row * HID + 64 + d] = mx;
}

// ---------------------------------------------------------------------------
// Host: full pipeline as a chain of kernel launches (graph-capturable).
// ---------------------------------------------------------------------------
extern "C" void kernel_launch(void* const* d_in, const int* in_sizes, int n_in,
                              void* d_out, int out_size) {
    const float* x_in  = (const float*)d_in[0];
    const float* fc1_W = (const float*)d_in[1];
    const float* fc1_b = (const float*)d_in[2];
    const float* fc2_W = (const float*)d_in[3];
    const float* fc2_b = (const float*)d_in[4];
    const float* gs_W  = (const float*)d_in[5];
    const float* gs_b  = (const float*)d_in[6];
    const float* gh_W  = (const float*)d_in[7];
    const float* gh_b  = (const float*)d_in[8];
    const float* go_W  = (const float*)d_in[9];
    const float* go_b  = (const float*)d_in[10];
    const float* d1_W  = (const float*)d_in[11];
    const float* d1_b  = (const float*)d_in[12];
    const float* d2_W  = (const float*)d_in[13];
    const float* d2_b  = (const float*)d_in[14];
    const float* d3_W  = (const float*)d_in[15];
    const float* d3_b  = (const float*)d_in[16];
    const float* fc3_W = (const float*)d_in[17];
    const float* fc3_b = (const float*)d_in[18];
    const float* fc4_W = (const float*)d_in[19];
    const float* fc4_b = (const float*)d_in[20];
    float* out = (float*)d_out;

    const int GB = NN / 32;   // 512 blocks (SIMT kernels)
    const int TB = NN / 128;  // 128 blocks (mma GEMMs)

    // fc1: x_in -> g_x(relu) [SIMT, KD=9]; fc2: g_x -> g_y(relu) [mma]
    gemm_k<9, 128, true><<<GB, 256>>>(x_in, -1, fc1_W, fc1_b, nullptr, 0);
    mmagemm_k<128, 128, true, false><<<TB, 256>>>(nullptr, 0, fc2_W, fc2_b, nullptr, 1);

    // x lives in g_y across layers; g_x is the ping-pong scratch.
    for (int i = 0; i < NLAYERS; ++i) {
        gemm4_k<false><<<GB, 128>>>(nullptr, 1, gs_W + i * HID * SPACE, gs_b + i * SPACE, nullptr, 4);
        mmagemm_k<128, 64, false, false><<<TB, 256>>>(nullptr, 1, gh_W + i * HID * PROP, gh_b + i * PROP, nullptr, 3);
        knn_k<<<NN / 8, 256>>>();
        agg_k<<<NN / 4, 256>>>();
        // lin_out: [g_y | g_agg] @ go_W -> g_x (no relu)
        mmagemm_k<256, 128, false, true><<<TB, 256>>>(nullptr, 0, go_W + i * 2 * HID * HID, go_b + i * HID, nullptr, 0);
        mmagemm_k<128, 128, true, false><<<TB, 256>>>(nullptr, 0, d1_W + i * HID * HID, d1_b + i * HID, nullptr, 1);
        mmagemm_k<128, 128, true, false><<<TB, 256>>>(nullptr, 1, d2_W + i * HID * HID, d2_b + i * HID, nullptr, 0);
        mmagemm_k<128, 128, true, false><<<TB, 256>>>(nullptr, 0, d3_W + i * HID * HID, d3_b + i * HID, nullptr, 1);
    }

    // fc3: g_y -> g_x(relu) [mma]; fc4: g_x -> out [SIMT small]
    mmagemm_k<128, 128, true, false><<<TB, 256>>>(nullptr, 1, fc3_W, fc3_b, nullptr, 0);
    gemm4_k<false><<<GB, 128>>>(nullptr, 0, fc4_W, fc4_b, out, -1);
}